// round 1
// baseline (speedup 1.0000x reference)
#include <cuda_runtime.h>

#define T_STEPS 512
#define BATCH   256
#define HID     64
#define DIN     300
#define G4      256                 // 4*H gates
#define MROWS   (T_STEPS * BATCH)   // 131072 time-major rows

// ---- scratch (allocation-free: device globals) ----
__device__ float g_xp [(size_t)MROWS * G4];   // input projection per layer
__device__ float g_hsA[(size_t)MROWS * HID];  // layer output ping
__device__ float g_hsB[(size_t)MROWS * HID];  // layer output pong

__device__ __forceinline__ float sigf(float x) {
    return __fdividef(1.f, 1.f + __expf(-x));
}
__device__ __forceinline__ float tanh_fast(float x) {
    return __fdividef(2.f, 1.f + __expf(-2.f * x)) - 1.f;
}

// ============================================================
// Generic fp32 GEMM: C[M,N] = act(A[M,K] @ W[N,K]^T + bias1 + bias2)
// GATHER=1: A row r maps to input[b][t][:] with r = t*BATCH + b (layer-0 transpose fused)
// ACT=1: tanh epilogue
// Tiles: BM=128, BN=64, BK=8, 256 threads, 8x4 micro-tile
// ============================================================
template<int GATHER, int ACT>
__global__ __launch_bounds__(256)
void gemm_kernel(const float* __restrict__ A, const float* __restrict__ W,
                 const float* __restrict__ bias1, const float* __restrict__ bias2,
                 float* __restrict__ C, int M, int N, int K)
{
    constexpr int BM = 128, BN = 64, BK = 8;
    __shared__ __align__(16) float As[BK][BM];
    __shared__ __align__(16) float Bs[BK][BN];

    const int tid   = threadIdx.x;
    const int mbase = blockIdx.x * BM;
    const int nbase = blockIdx.y * BN;

    const int arow = tid >> 1;           // 0..127
    const int acol = (tid & 1) * 4;      // 0 or 4
    const int wrow = tid >> 1;           // 0..63 (tid<128 only)
    const int wcol = (tid & 1) * 4;
    const int tx = tid & 15;             // N dir
    const int ty = tid >> 4;             // M dir

    long arow_off;
    {
        int gr = mbase + arow;
        if (GATHER) {
            int b = gr & (BATCH - 1);
            int t = gr >> 8;
            arow_off = (long)(b * T_STEPS + t) * K;
        } else {
            arow_off = (long)gr * K;
        }
    }

    const int KT = (K + BK - 1) / BK;
    float a_ld[4], w_ld[4];

    // prefetch tile 0
    {
#pragma unroll
        for (int i = 0; i < 4; i++) {
            int k = acol + i;
            a_ld[i] = (k < K) ? A[arow_off + k] : 0.f;
        }
        if (tid < 128) {
            int n = nbase + wrow;
#pragma unroll
            for (int i = 0; i < 4; i++) {
                int k = wcol + i;
                w_ld[i] = (n < N && k < K) ? W[(long)n * K + k] : 0.f;
            }
        }
    }

    float acc[8][4];
#pragma unroll
    for (int i = 0; i < 8; i++)
#pragma unroll
        for (int j = 0; j < 4; j++) acc[i][j] = 0.f;

    for (int kt = 0; kt < KT; kt++) {
#pragma unroll
        for (int i = 0; i < 4; i++) As[acol + i][arow] = a_ld[i];
        if (tid < 128) {
#pragma unroll
            for (int i = 0; i < 4; i++) Bs[wcol + i][wrow] = w_ld[i];
        }
        __syncthreads();

        if (kt + 1 < KT) {
            int kb = (kt + 1) * BK;
#pragma unroll
            for (int i = 0; i < 4; i++) {
                int k = kb + acol + i;
                a_ld[i] = (k < K) ? A[arow_off + k] : 0.f;
            }
            if (tid < 128) {
                int n = nbase + wrow;
#pragma unroll
                for (int i = 0; i < 4; i++) {
                    int k = kb + wcol + i;
                    w_ld[i] = (n < N && k < K) ? W[(long)n * K + k] : 0.f;
                }
            }
        }

#pragma unroll
        for (int kk = 0; kk < BK; kk++) {
            float4 a0 = *(const float4*)&As[kk][ty * 8];
            float4 a1 = *(const float4*)&As[kk][ty * 8 + 4];
            float4 b0 = *(const float4*)&Bs[kk][tx * 4];
            float am[8] = {a0.x, a0.y, a0.z, a0.w, a1.x, a1.y, a1.z, a1.w};
            float bn[4] = {b0.x, b0.y, b0.z, b0.w};
#pragma unroll
            for (int i = 0; i < 8; i++)
#pragma unroll
                for (int j = 0; j < 4; j++)
                    acc[i][j] += am[i] * bn[j];
        }
        __syncthreads();
    }

    // epilogue
    const int n0 = nbase + tx * 4;
    float bb[4];
#pragma unroll
    for (int j = 0; j < 4; j++) {
        int n = n0 + j;
        float b = 0.f;
        if (n < N) {
            b = bias1[n];
            if (bias2) b += bias2[n];
        }
        bb[j] = b;
    }
#pragma unroll
    for (int i = 0; i < 8; i++) {
        int r = mbase + ty * 8 + i;
#pragma unroll
        for (int j = 0; j < 4; j++) {
            int n = n0 + j;
            if (n < N) {
                float v = acc[i][j] + bb[j];
                if (ACT) v = tanh_fast(v);
                C[(long)r * N + n] = v;
            }
        }
    }
}

// ============================================================
// LSTM recurrence, one layer. Batch-parallel: 128 blocks x 2 batch rows.
// Thread tid owns gate column tid; Whh column lives in registers.
// xp already contains x@Wih^T + bih + bhh (time-major [T,B,256]).
// Gate order (torch): [0:64)=i, [64:128)=f, [128:192)=g, [192:256)=o
// ============================================================
__global__ __launch_bounds__(256)
void lstm_rec_kernel(const float* __restrict__ xp, const float* __restrict__ whh,
                     const float* __restrict__ h0, const float* __restrict__ c0,
                     float* __restrict__ hs, float* __restrict__ hn, float* __restrict__ cn)
{
    __shared__ __align__(16) float h_s[2][HID];
    __shared__ __align__(16) float gate_s[2][G4];

    const int tid = threadIdx.x;
    const int b0  = blockIdx.x * 2;
    const int gc  = tid;

    // Whh row gc -> registers
    float w[HID];
#pragma unroll
    for (int k4 = 0; k4 < 16; k4++) {
        float4 v = *(const float4*)(whh + (long)gc * HID + k4 * 4);
        w[4 * k4 + 0] = v.x; w[4 * k4 + 1] = v.y;
        w[4 * k4 + 2] = v.z; w[4 * k4 + 3] = v.w;
    }

    const int cb = tid >> 6;    // combine-phase batch (tid<128)
    const int cj = tid & 63;    // combine-phase hidden idx
    float c_reg = 0.f;
    if (tid < 128) {
        h_s[cb][cj] = h0[(b0 + cb) * HID + cj];
        c_reg       = c0[(b0 + cb) * HID + cj];
    }
    __syncthreads();

    const int gtype = gc >> 6;
    // xp offset for (t, b0+{0,1}, gc)
    float pre0 = xp[((long)0 * BATCH + b0) * G4 + gc];
    float pre1 = xp[((long)0 * BATCH + b0 + 1) * G4 + gc];

    for (int t = 0; t < T_STEPS; t++) {
        float cur0 = pre0, cur1 = pre1;
        if (t + 1 < T_STEPS) {
            long base = ((long)(t + 1) * BATCH + b0) * G4 + gc;
            pre0 = xp[base];
            pre1 = xp[base + G4];
        }

        float a0 = 0.f, a1 = 0.f, a2 = 0.f, a3 = 0.f;
        const float4* hv0 = (const float4*)h_s[0];
        const float4* hv1 = (const float4*)h_s[1];
#pragma unroll
        for (int k4 = 0; k4 < 16; k4++) {
            float4 x0 = hv0[k4];
            float4 x1 = hv1[k4];
            a0 += w[4 * k4 + 0] * x0.x + w[4 * k4 + 1] * x0.y;
            a2 += w[4 * k4 + 2] * x0.z + w[4 * k4 + 3] * x0.w;
            a1 += w[4 * k4 + 0] * x1.x + w[4 * k4 + 1] * x1.y;
            a3 += w[4 * k4 + 2] * x1.z + w[4 * k4 + 3] * x1.w;
        }
        float z0 = cur0 + a0 + a2;
        float z1 = cur1 + a1 + a3;

        float v0, v1;
        if (gtype == 2) { v0 = tanh_fast(z0); v1 = tanh_fast(z1); }
        else            { v0 = sigf(z0);      v1 = sigf(z1);      }
        gate_s[0][gc] = v0;
        gate_s[1][gc] = v1;
        __syncthreads();

        if (tid < 128) {
            float ig = gate_s[cb][cj];
            float fg = gate_s[cb][64 + cj];
            float gg = gate_s[cb][128 + cj];
            float og = gate_s[cb][192 + cj];
            c_reg = fg * c_reg + ig * gg;
            float h = og * tanh_fast(c_reg);
            h_s[cb][cj] = h;
            hs[((long)t * BATCH + b0 + cb) * HID + cj] = h;
        }
        __syncthreads();
    }

    if (tid < 128) {
        if (hn) hn[(b0 + cb) * HID + cj] = h_s[cb][cj];
        if (cn) cn[(b0 + cb) * HID + cj] = c_reg;
    }
}

// ============================================================
extern "C" void kernel_launch(void* const* d_in, const int* in_sizes, int n_in,
                              void* d_out, int out_size)
{
    const float* input = (const float*)d_in[0];
    const float* h_0   = (const float*)d_in[1];
    const float* c_0   = (const float*)d_in[2];
    const float* wih[3] = {(const float*)d_in[3],  (const float*)d_in[7],  (const float*)d_in[11]};
    const float* whh[3] = {(const float*)d_in[4],  (const float*)d_in[8],  (const float*)d_in[12]};
    const float* bih[3] = {(const float*)d_in[5],  (const float*)d_in[9],  (const float*)d_in[13]};
    const float* bhh[3] = {(const float*)d_in[6],  (const float*)d_in[10], (const float*)d_in[14]};
    const float* w1 = (const float*)d_in[15];
    const float* b1 = (const float*)d_in[16];
    const float* w2 = (const float*)d_in[17];
    const float* b2 = (const float*)d_in[18];
    float* out = (float*)d_out;

    float *xp, *hsA, *hsB;
    cudaGetSymbolAddress((void**)&xp,  g_xp);
    cudaGetSymbolAddress((void**)&hsA, g_hsA);
    cudaGetSymbolAddress((void**)&hsB, g_hsB);

    // optional h_n / c_n outputs appended after `out`
    float* hn = nullptr;
    float* cn = nullptr;
    const long out_main = (long)MROWS * DIN;             // 39,321,600
    if ((long)out_size >= out_main + 6L * BATCH * HID) {
        hn = out + out_main;
        cn = hn + 3 * BATCH * HID;
    }

    const dim3 thr(256);
    const dim3 gN256(MROWS / 128, G4 / 64);   // (1024, 4)
    const dim3 gN64 (MROWS / 128, 1);
    const dim3 gN300(MROWS / 128, (DIN + 63) / 64);  // (1024, 5)

    // ---- layer 0 ----
    gemm_kernel<1, 0><<<gN256, thr>>>(input, wih[0], bih[0], bhh[0], xp, MROWS, G4, DIN);
    lstm_rec_kernel<<<BATCH / 2, thr>>>(xp, whh[0], h_0, c_0, hsA,
                                        hn ? hn : nullptr, cn ? cn : nullptr);
    // ---- layer 1 ----
    gemm_kernel<0, 0><<<gN256, thr>>>(hsA, wih[1], bih[1], bhh[1], xp, MROWS, G4, HID);
    lstm_rec_kernel<<<BATCH / 2, thr>>>(xp, whh[1],
                                        h_0 + BATCH * HID, c_0 + BATCH * HID, hsB,
                                        hn ? hn + BATCH * HID : nullptr,
                                        cn ? cn + BATCH * HID : nullptr);
    // ---- layer 2 ----
    gemm_kernel<0, 0><<<gN256, thr>>>(hsB, wih[2], bih[2], bhh[2], xp, MROWS, G4, HID);
    lstm_rec_kernel<<<BATCH / 2, thr>>>(xp, whh[2],
                                        h_0 + 2 * BATCH * HID, c_0 + 2 * BATCH * HID, hsA,
                                        hn ? hn + 2 * BATCH * HID : nullptr,
                                        cn ? cn + 2 * BATCH * HID : nullptr);
    // ---- MLP head ----
    gemm_kernel<0, 1><<<gN64,  thr>>>(hsA, w1, b1, nullptr, hsB, MROWS, HID, HID);
    gemm_kernel<0, 0><<<gN300, thr>>>(hsB, w2, b2, nullptr, out, MROWS, DIN, HID);
}